// round 3
// baseline (speedup 1.0000x reference)
#include <cuda_runtime.h>

#define Bn 256
#define Sn 336
#define Cn 321
#define Hn 512
#define Pn 96

// Scratch [b][c][h]: IT after it_kernel, overwritten in place with h_b by the
// recurrence. 256*321*512*4B = 168.3 MB static device scratch (allowed).
__device__ float g_scr[(size_t)Bn * Cn * Hn];

// ---- packed f32x2 helpers (sm_103a) ---------------------------------------
__device__ __forceinline__ void fma2(unsigned long long &d,
                                     unsigned long long a,
                                     unsigned long long b) {
    asm("fma.rn.f32x2 %0, %1, %2, %0;" : "+l"(d) : "l"(a), "l"(b));
}
__device__ __forceinline__ unsigned long long dup2(float v) {
    unsigned long long r;
    asm("mov.b64 %0, {%1, %1};" : "=l"(r) : "f"(v));
    return r;
}
__device__ __forceinline__ float2 up2(unsigned long long v) {
    float2 r;
    asm("mov.b64 {%0, %1}, %2;" : "=f"(r.x), "=f"(r.y) : "l"(v));
    return r;
}
// NaN-PROPAGATING relu (matches jnp.maximum(x, 0) semantics: NaN stays NaN).
__device__ __forceinline__ float reluN(float x) { return (x < 0.f) ? 0.f : x; }

// ============================================================================
// Kernel 1: IT[b,c,h] = bi[h] + sum_s x[b,s,c] * Wi[h,s]
// Tile 64(c) x 64(h), Kt=16 over S=336 (21 iters), 128 threads, micro 4c x 8h.
// ============================================================================
__global__ void __launch_bounds__(128) it_kernel(
    const float* __restrict__ x,    // [B,S,C]
    const float* __restrict__ Wi,   // [H,S]
    const float* __restrict__ bi)   // [H]
{
    __shared__ __align__(16) float As[16][68];  // As[kk][c]
    __shared__ __align__(16) float Bs[16][68];  // Bs[kk][h]

    const int b  = blockIdx.z;
    const int n0 = blockIdx.x * 64;
    const int m0 = blockIdx.y * 64;
    const int t  = threadIdx.x;
    const int tm = t & 15;   // 16 x 4c = 64
    const int tn = t >> 4;   // 8 x 8h = 64

    unsigned long long acc[4][4];
#pragma unroll
    for (int i = 0; i < 4; i++)
#pragma unroll
        for (int j = 0; j < 4; j++) acc[i][j] = 0ull;

    const float* xb = x + (size_t)b * Sn * Cn;
    const int la_k = t >> 3;         // 0..15
    const int la_c = (t & 7) * 8;    // 0..56
    const int lb_n = t & 63;
    const int lb_k = (t >> 6) * 8;   // 0 or 8

    for (int k0 = 0; k0 < Sn; k0 += 16) {
        // A tile: x[b][k0+la_k][m0+la_c .. +8)  (c-contiguous, coalesced)
        {
            const float* src = xb + (size_t)(k0 + la_k) * Cn + m0 + la_c;
#pragma unroll
            for (int j = 0; j < 8; j++)
                As[la_k][la_c + j] = (m0 + la_c + j < Cn) ? src[j] : 0.f;
        }
        // B tile: Wi[n0+lb_n][k0+lb_k .. +8)
        {
            const float* src = Wi + (size_t)(n0 + lb_n) * Sn + k0 + lb_k;
            float4 v0 = *(const float4*)(src);
            float4 v1 = *(const float4*)(src + 4);
            Bs[lb_k + 0][lb_n] = v0.x; Bs[lb_k + 1][lb_n] = v0.y;
            Bs[lb_k + 2][lb_n] = v0.z; Bs[lb_k + 3][lb_n] = v0.w;
            Bs[lb_k + 4][lb_n] = v1.x; Bs[lb_k + 5][lb_n] = v1.y;
            Bs[lb_k + 6][lb_n] = v1.z; Bs[lb_k + 7][lb_n] = v1.w;
        }
        __syncthreads();
#pragma unroll
        for (int kk = 0; kk < 16; kk++) {
            float4 a = *(const float4*)&As[kk][tm * 4];
            const unsigned long long* bp =
                (const unsigned long long*)&Bs[kk][tn * 8];
            unsigned long long b0 = bp[0], b1 = bp[1], b2 = bp[2], b3 = bp[3];
            unsigned long long a0 = dup2(a.x), a1 = dup2(a.y),
                               a2 = dup2(a.z), a3 = dup2(a.w);
            fma2(acc[0][0], a0, b0); fma2(acc[0][1], a0, b1);
            fma2(acc[0][2], a0, b2); fma2(acc[0][3], a0, b3);
            fma2(acc[1][0], a1, b0); fma2(acc[1][1], a1, b1);
            fma2(acc[1][2], a1, b2); fma2(acc[1][3], a1, b3);
            fma2(acc[2][0], a2, b0); fma2(acc[2][1], a2, b1);
            fma2(acc[2][2], a2, b2); fma2(acc[2][3], a2, b3);
            fma2(acc[3][0], a3, b0); fma2(acc[3][1], a3, b1);
            fma2(acc[3][2], a3, b2); fma2(acc[3][3], a3, b3);
        }
        __syncthreads();
    }

    float biv[8];
#pragma unroll
    for (int j = 0; j < 8; j++) biv[j] = bi[n0 + tn * 8 + j];

#pragma unroll
    for (int i = 0; i < 4; i++) {
        int c = m0 + tm * 4 + i;
        if (c < Cn) {
            float* dst = g_scr + ((size_t)b * Cn + c) * Hn + n0 + tn * 8;
#pragma unroll
            for (int j = 0; j < 4; j++) {
                float2 v = up2(acc[i][j]);
                dst[2 * j]     = v.x + biv[2 * j];
                dst[2 * j + 1] = v.y + biv[2 * j + 1];
            }
        }
    }
}

// ============================================================================
// Kernel 2: step 0 (h_prev = 0 -> hh = bh), elementwise in place on g_scr[0].
// ============================================================================
__global__ void step0_kernel(const float* __restrict__ bh) {
    int i = blockIdx.x * blockDim.x + threadIdx.x;
    if (i < Cn * Hn) {
        float it = g_scr[i];
        float hh = bh[i & (Hn - 1)];
        float a  = reluN(it + hh);
        g_scr[i] = reluN(a + hh);
    }
}

// ============================================================================
// Kernel 3: one recurrence step b (1..255):
//   hh[c,n] = bh[n] + sum_k h_{b-1}[c,k] * Wh[n,k]
//   a = reluN(it + hh); h_b = reluN(a + hh)   (in place on g_scr[b])
// Tile 32(c) x 64(n), Kt=32 over K=512, 128 threads, micro 4c x 4n.
// Grid (8, 11) = 88 CTAs.
// ============================================================================
__global__ void __launch_bounds__(128) step_kernel(
    const float* __restrict__ Wh,   // [H,H]
    const float* __restrict__ bh,   // [H]
    int b)
{
    __shared__ __align__(16) float As[32][36];  // As[kk][c]
    __shared__ __align__(16) float Bs[32][68];  // Bs[kk][n]

    const int n0 = blockIdx.x * 64;
    const int m0 = blockIdx.y * 32;
    const int t  = threadIdx.x;
    const int tm = t & 7;    // 8 x 4c = 32
    const int tn = t >> 3;   // 16 x 4n = 64

    unsigned long long acc[4][2];
#pragma unroll
    for (int i = 0; i < 4; i++) { acc[i][0] = 0ull; acc[i][1] = 0ull; }

    const float* hprev = g_scr + (size_t)(b - 1) * Cn * Hn;
    const int la_c = t >> 2;          // 0..31
    const int la_k = (t & 3) * 8;     // 0,8,16,24
    const int lb_n = t & 63;
    const int lb_k = (t >> 6) * 16;   // 0 or 16

    for (int k0 = 0; k0 < Hn; k0 += 32) {
        // A tile: h_prev[m0+la_c][k0+la_k .. +8)
        {
            int c = m0 + la_c;
            if (c < Cn) {
                const float* src = hprev + (size_t)c * Hn + k0 + la_k;
                float4 v0 = *(const float4*)(src);
                float4 v1 = *(const float4*)(src + 4);
                As[la_k + 0][la_c] = v0.x; As[la_k + 1][la_c] = v0.y;
                As[la_k + 2][la_c] = v0.z; As[la_k + 3][la_c] = v0.w;
                As[la_k + 4][la_c] = v1.x; As[la_k + 5][la_c] = v1.y;
                As[la_k + 6][la_c] = v1.z; As[la_k + 7][la_c] = v1.w;
            } else {
#pragma unroll
                for (int j = 0; j < 8; j++) As[la_k + j][la_c] = 0.f;
            }
        }
        // B tile: Wh[n0+lb_n][k0+lb_k .. +16)
        {
            const float* src = Wh + (size_t)(n0 + lb_n) * Hn + k0 + lb_k;
#pragma unroll
            for (int g = 0; g < 4; g++) {
                float4 v = *(const float4*)(src + g * 4);
                Bs[lb_k + g * 4 + 0][lb_n] = v.x;
                Bs[lb_k + g * 4 + 1][lb_n] = v.y;
                Bs[lb_k + g * 4 + 2][lb_n] = v.z;
                Bs[lb_k + g * 4 + 3][lb_n] = v.w;
            }
        }
        __syncthreads();
#pragma unroll
        for (int kk = 0; kk < 32; kk++) {
            float4 a = *(const float4*)&As[kk][tm * 4];
            ulonglong2 bb = *(const ulonglong2*)&Bs[kk][tn * 4];
            unsigned long long a0 = dup2(a.x), a1 = dup2(a.y),
                               a2 = dup2(a.z), a3 = dup2(a.w);
            fma2(acc[0][0], a0, bb.x); fma2(acc[0][1], a0, bb.y);
            fma2(acc[1][0], a1, bb.x); fma2(acc[1][1], a1, bb.y);
            fma2(acc[2][0], a2, bb.x); fma2(acc[2][1], a2, bb.y);
            fma2(acc[3][0], a3, bb.x); fma2(acc[3][1], a3, bb.y);
        }
        __syncthreads();
    }

    float bhv[4];
#pragma unroll
    for (int j = 0; j < 4; j++) bhv[j] = bh[n0 + tn * 4 + j];

    float* itrow = g_scr + (size_t)b * Cn * Hn;
#pragma unroll
    for (int i = 0; i < 4; i++) {
        int c = m0 + tm * 4 + i;
        if (c < Cn) {
            float* row = itrow + (size_t)c * Hn + n0 + tn * 4;
            float2 v0 = up2(acc[i][0]);
            float2 v1 = up2(acc[i][1]);
            float hhv[4] = { v0.x + bhv[0], v0.y + bhv[1],
                             v1.x + bhv[2], v1.y + bhv[3] };
#pragma unroll
            for (int j = 0; j < 4; j++) {
                float it = row[j];
                float a  = reluN(it + hhv[j]);
                row[j]   = reluN(a + hhv[j]);
            }
        }
    }
}

// ============================================================================
// Kernel 4: out[b,p,c] = (bf[p] + sum_k h_b[c,k]*Wf[p,k] >= 0) ? 1 : 0
// (sigmoid(z) >= 0.5  <=>  z >= 0; NaN -> false -> 0, matching jnp.where)
// Tile 32(c) x 96(p), Kt=16 over K=512, 192 threads, micro 4c x 4p.
// Grid (11, 256).
// ============================================================================
__global__ void __launch_bounds__(192) final_kernel(
    const float* __restrict__ Wf,   // [P,H]
    const float* __restrict__ bf,   // [P]
    float* __restrict__ out)        // [B,P,C]
{
    __shared__ __align__(16) float As[16][36];   // As[kk][c]
    __shared__ __align__(16) float Bs[16][100];  // Bs[kk][p]

    const int b  = blockIdx.y;
    const int m0 = blockIdx.x * 32;
    const int t  = threadIdx.x;
    const int tm = t & 7;    // 8 x 4c = 32
    const int tn = t >> 3;   // 24 x 4p = 96

    unsigned long long acc[4][2];
#pragma unroll
    for (int i = 0; i < 4; i++) { acc[i][0] = 0ull; acc[i][1] = 0ull; }

    const float* hb = g_scr + (size_t)b * Cn * Hn;
    const int la_c = t >> 2;        // 0..31 (threads 0..127 only)
    const int la_k = (t & 3) * 4;   // 0,4,8,12
    const int lb_p = t % 96;
    const int lb_k = (t / 96) * 8;  // 0 or 8

    for (int k0 = 0; k0 < Hn; k0 += 16) {
        if (t < 128) {
            int c = m0 + la_c;
            if (c < Cn) {
                float4 v = *(const float4*)(hb + (size_t)c * Hn + k0 + la_k);
                As[la_k + 0][la_c] = v.x; As[la_k + 1][la_c] = v.y;
                As[la_k + 2][la_c] = v.z; As[la_k + 3][la_c] = v.w;
            } else {
#pragma unroll
                for (int j = 0; j < 4; j++) As[la_k + j][la_c] = 0.f;
            }
        }
        {
            const float* src = Wf + (size_t)lb_p * Hn + k0 + lb_k;
            float4 v0 = *(const float4*)(src);
            float4 v1 = *(const float4*)(src + 4);
            Bs[lb_k + 0][lb_p] = v0.x; Bs[lb_k + 1][lb_p] = v0.y;
            Bs[lb_k + 2][lb_p] = v0.z; Bs[lb_k + 3][lb_p] = v0.w;
            Bs[lb_k + 4][lb_p] = v1.x; Bs[lb_k + 5][lb_p] = v1.y;
            Bs[lb_k + 6][lb_p] = v1.z; Bs[lb_k + 7][lb_p] = v1.w;
        }
        __syncthreads();
#pragma unroll
        for (int kk = 0; kk < 16; kk++) {
            float4 a = *(const float4*)&As[kk][tm * 4];
            ulonglong2 bb = *(const ulonglong2*)&Bs[kk][tn * 4];
            unsigned long long a0 = dup2(a.x), a1 = dup2(a.y),
                               a2 = dup2(a.z), a3 = dup2(a.w);
            fma2(acc[0][0], a0, bb.x); fma2(acc[0][1], a0, bb.y);
            fma2(acc[1][0], a1, bb.x); fma2(acc[1][1], a1, bb.y);
            fma2(acc[2][0], a2, bb.x); fma2(acc[2][1], a2, bb.y);
            fma2(acc[3][0], a3, bb.x); fma2(acc[3][1], a3, bb.y);
        }
        __syncthreads();
    }

    float bfv[4];
#pragma unroll
    for (int j = 0; j < 4; j++) bfv[j] = bf[tn * 4 + j];

#pragma unroll
    for (int i = 0; i < 4; i++) {
        int c = m0 + tm * 4 + i;
        if (c < Cn) {
            float2 v0 = up2(acc[i][0]);
            float2 v1 = up2(acc[i][1]);
            float z[4] = { v0.x + bfv[0], v0.y + bfv[1],
                           v1.x + bfv[2], v1.y + bfv[3] };
            size_t base = ((size_t)b * Pn + tn * 4) * Cn + c;
#pragma unroll
            for (int j = 0; j < 4; j++)
                out[base + (size_t)j * Cn] = (z[j] >= 0.f) ? 1.f : 0.f;
        }
    }
}

// ============================================================================
extern "C" void kernel_launch(void* const* d_in, const int* in_sizes, int n_in,
                              void* d_out, int out_size) {
    const float* x  = (const float*)d_in[0];
    const float* Wi = (const float*)d_in[1];
    const float* bi = (const float*)d_in[2];
    const float* Wh = (const float*)d_in[3];
    const float* bh = (const float*)d_in[4];
    const float* Wf = (const float*)d_in[5];
    const float* bf = (const float*)d_in[6];
    float* out = (float*)d_out;

    // 1) IT = x permuted @ Wi^T + bi  for all b   -> g_scr
    it_kernel<<<dim3(8, 6, Bn), 128>>>(x, Wi, bi);

    // 2) recurrence over batch dim (sequential)
    step0_kernel<<<(Cn * Hn + 255) / 256, 256>>>(bh);
    for (int b = 1; b < Bn; b++)
        step_kernel<<<dim3(8, 11), 128>>>(Wh, bh, b);

    // 3) thresholded output GEMM
    final_kernel<<<dim3(11, Bn), 192>>>(Wf, bf, out);
}

// round 4
// speedup vs baseline: 1.7057x; 1.7057x over previous
#include <cuda_runtime.h>

#define Bn 256
#define Sn 336
#define Cn 321
#define Hn 512
#define Pn 96
#define NCTA 88
#define KT 64

typedef unsigned long long ull;

__device__ float    g_scr[(size_t)Bn * Cn * Hn];
__device__ unsigned g_bar;

__device__ __forceinline__ void fma2(ull &d, ull a, ull b) {
    asm("fma.rn.f32x2 %0, %1, %2, %0;" : "+l"(d) : "l"(a), "l"(b));
}
__device__ __forceinline__ ull dup2(float v) {
    ull r; asm("mov.b64 %0, {%1, %1};" : "=l"(r) : "f"(v)); return r;
}
__device__ __forceinline__ float2 up2(ull v) {
    float2 r; asm("mov.b64 {%0, %1}, %2;" : "=f"(r.x), "=f"(r.y) : "l"(v)); return r;
}
__device__ __forceinline__ float reluN(float x) { return (x < 0.f) ? 0.f : x; }

__global__ void reset_bar_kernel() { g_bar = 0u; }

// ============================================================================
// it_kernel: IT[b,c,h] = bi[h] + sum_s x[b,s,c]*Wi[h,s]   (v1, proven)
// ============================================================================
__global__ void __launch_bounds__(128) it_kernel(
    const float* __restrict__ x, const float* __restrict__ Wi,
    const float* __restrict__ bi)
{
    __shared__ __align__(16) float As[16][68];
    __shared__ __align__(16) float Bs[16][68];
    const int b  = blockIdx.z;
    const int n0 = blockIdx.x * 64;
    const int m0 = blockIdx.y * 64;
    const int t  = threadIdx.x;
    const int tm = t & 15, tn = t >> 4;

    ull acc[4][4];
#pragma unroll
    for (int i = 0; i < 4; i++)
#pragma unroll
        for (int j = 0; j < 4; j++) acc[i][j] = 0ull;

    const float* xb = x + (size_t)b * Sn * Cn;
    const int la_k = t >> 3, la_c = (t & 7) * 8;
    const int lb_n = t & 63, lb_k = (t >> 6) * 8;

    for (int k0 = 0; k0 < Sn; k0 += 16) {
        {
            const float* src = xb + (size_t)(k0 + la_k) * Cn + m0 + la_c;
#pragma unroll
            for (int j = 0; j < 8; j++)
                As[la_k][la_c + j] = (m0 + la_c + j < Cn) ? src[j] : 0.f;
        }
        {
            const float* src = Wi + (size_t)(n0 + lb_n) * Sn + k0 + lb_k;
            float4 v0 = *(const float4*)(src);
            float4 v1 = *(const float4*)(src + 4);
            Bs[lb_k + 0][lb_n] = v0.x; Bs[lb_k + 1][lb_n] = v0.y;
            Bs[lb_k + 2][lb_n] = v0.z; Bs[lb_k + 3][lb_n] = v0.w;
            Bs[lb_k + 4][lb_n] = v1.x; Bs[lb_k + 5][lb_n] = v1.y;
            Bs[lb_k + 6][lb_n] = v1.z; Bs[lb_k + 7][lb_n] = v1.w;
        }
        __syncthreads();
#pragma unroll
        for (int kk = 0; kk < 16; kk++) {
            float4 a = *(const float4*)&As[kk][tm * 4];
            const ull* bp = (const ull*)&Bs[kk][tn * 8];
            ull b0 = bp[0], b1 = bp[1], b2 = bp[2], b3 = bp[3];
            ull a0 = dup2(a.x), a1 = dup2(a.y), a2 = dup2(a.z), a3 = dup2(a.w);
            fma2(acc[0][0], a0, b0); fma2(acc[0][1], a0, b1);
            fma2(acc[0][2], a0, b2); fma2(acc[0][3], a0, b3);
            fma2(acc[1][0], a1, b0); fma2(acc[1][1], a1, b1);
            fma2(acc[1][2], a1, b2); fma2(acc[1][3], a1, b3);
            fma2(acc[2][0], a2, b0); fma2(acc[2][1], a2, b1);
            fma2(acc[2][2], a2, b2); fma2(acc[2][3], a2, b3);
            fma2(acc[3][0], a3, b0); fma2(acc[3][1], a3, b1);
            fma2(acc[3][2], a3, b2); fma2(acc[3][3], a3, b3);
        }
        __syncthreads();
    }
    float biv[8];
#pragma unroll
    for (int j = 0; j < 8; j++) biv[j] = bi[n0 + tn * 8 + j];
#pragma unroll
    for (int i = 0; i < 4; i++) {
        int c = m0 + tm * 4 + i;
        if (c < Cn) {
            float* dst = g_scr + ((size_t)b * Cn + c) * Hn + n0 + tn * 8;
#pragma unroll
            for (int j = 0; j < 4; j++) {
                float2 v = up2(acc[i][j]);
                dst[2 * j]     = v.x + biv[2 * j];
                dst[2 * j + 1] = v.y + biv[2 * j + 1];
            }
        }
    }
}

// ============================================================================
// Persistent recurrence: 88 CTAs, CTA owns tile (m0:32c, n0:64n), Wh resident.
// smem: Bs[512][64] (128KB) + As[2][64][36] (18KB) = 146KB dynamic.
// ============================================================================
__device__ __forceinline__ void gbar(unsigned target) {
    __syncthreads();
    if (threadIdx.x == 0) {
        asm volatile("red.release.gpu.global.add.u32 [%0], 1;"
                     :: "l"(&g_bar) : "memory");
        unsigned v;
        do {
            asm volatile("ld.acquire.gpu.global.u32 %0, [%1];"
                         : "=r"(v) : "l"(&g_bar));
        } while (v < target);
    }
    __syncthreads();
}

extern __shared__ float sm_dyn[];

__global__ void __launch_bounds__(128) rnn_kernel(
    const float* __restrict__ Wh, const float* __restrict__ bh)
{
    float* Bs = sm_dyn;                 // Bs[k][n] : k*64+n
    float* As = sm_dyn + 512 * 64;      // As[buf][kk][c]: buf*64*36+kk*36+c
    const int t   = threadIdx.x;
    const int cta = blockIdx.x;
    const int n0  = (cta & 7) * 64;
    const int m0  = (cta >> 3) * 32;
    const int tm  = t & 7, tn = t >> 3;

    // Wh tile transposed into smem: Bs[k][n] = Wh[n0+n][k]
    {
        const int n = t & 63, kb = (t >> 6) * 256;
        const float* src = Wh + (size_t)(n0 + n) * Hn + kb;
        for (int k = 0; k < 256; k += 4) {
            float4 v = *(const float4*)(src + k);
            Bs[(kb + k + 0) * 64 + n] = v.x; Bs[(kb + k + 1) * 64 + n] = v.y;
            Bs[(kb + k + 2) * 64 + n] = v.z; Bs[(kb + k + 3) * 64 + n] = v.w;
        }
    }
    float bhv[4];
#pragma unroll
    for (int j = 0; j < 4; j++) bhv[j] = bh[n0 + tn * 4 + j];
    __syncthreads();

    // step 0: h0 = reluN(reluN(it+bh)+bh) elementwise on own tile
#pragma unroll
    for (int i = 0; i < 4; i++) {
        int c = m0 + tm * 4 + i;
        if (c < Cn) {
            float* row = g_scr + (size_t)c * Hn + n0 + tn * 4;
            float4 itv = *(const float4*)row;
            float f[4] = { itv.x, itv.y, itv.z, itv.w };
#pragma unroll
            for (int j = 0; j < 4; j++) {
                float a = reluN(f[j] + bhv[j]);
                f[j] = reluN(a + bhv[j]);
            }
            *(float4*)row = make_float4(f[0], f[1], f[2], f[3]);
        }
    }
    gbar(NCTA);

    const int la_c = t >> 2;          // 0..31
    const int la_k = (t & 3) * 16;    // 0,16,32,48

    for (int b = 1; b < Bn; b++) {
        const float* hp = g_scr + (size_t)(b - 1) * (Cn * Hn);
        const float* arow = hp + (size_t)(m0 + la_c) * Hn;
        ull acc[4][2];
#pragma unroll
        for (int i = 0; i < 4; i++) { acc[i][0] = 0ull; acc[i][1] = 0ull; }

        float4 pre[4];
#pragma unroll
        for (int g = 0; g < 4; g++)
            pre[g] = *(const float4*)(arow + la_k + g * 4);
        {
            float* d = As + 0;  // buf 0
#pragma unroll
            for (int g = 0; g < 4; g++) {
                d[(la_k + g * 4 + 0) * 36 + la_c] = pre[g].x;
                d[(la_k + g * 4 + 1) * 36 + la_c] = pre[g].y;
                d[(la_k + g * 4 + 2) * 36 + la_c] = pre[g].z;
                d[(la_k + g * 4 + 3) * 36 + la_c] = pre[g].w;
            }
        }
        __syncthreads();

        for (int ch = 0; ch < 8; ch++) {
            if (ch < 7) {
                const float* s = arow + (ch + 1) * KT + la_k;
#pragma unroll
                for (int g = 0; g < 4; g++) pre[g] = *(const float4*)(s + g * 4);
            }
            const float* as = As + (ch & 1) * (KT * 36);
            const float* bs = Bs + (ch * KT) * 64 + tn * 4;
#pragma unroll 16
            for (int kk = 0; kk < KT; kk++) {
                float4 a = *(const float4*)(as + kk * 36 + tm * 4);
                ulonglong2 bb = *(const ulonglong2*)(bs + kk * 64);
                ull a0 = dup2(a.x), a1 = dup2(a.y),
                    a2 = dup2(a.z), a3 = dup2(a.w);
                fma2(acc[0][0], a0, bb.x); fma2(acc[0][1], a0, bb.y);
                fma2(acc[1][0], a1, bb.x); fma2(acc[1][1], a1, bb.y);
                fma2(acc[2][0], a2, bb.x); fma2(acc[2][1], a2, bb.y);
                fma2(acc[3][0], a3, bb.x); fma2(acc[3][1], a3, bb.y);
            }
            if (ch < 7) {
                float* d = As + ((ch + 1) & 1) * (KT * 36);
#pragma unroll
                for (int g = 0; g < 4; g++) {
                    d[(la_k + g * 4 + 0) * 36 + la_c] = pre[g].x;
                    d[(la_k + g * 4 + 1) * 36 + la_c] = pre[g].y;
                    d[(la_k + g * 4 + 2) * 36 + la_c] = pre[g].z;
                    d[(la_k + g * 4 + 3) * 36 + la_c] = pre[g].w;
                }
            }
            __syncthreads();
        }

        // epilogue: h_b = reluN(reluN(it+hh)+hh), in place on g_scr[b]
        float* itrow = g_scr + (size_t)b * (Cn * Hn);
#pragma unroll
        for (int i = 0; i < 4; i++) {
            int c = m0 + tm * 4 + i;
            if (c < Cn) {
                float* row = itrow + (size_t)c * Hn + n0 + tn * 4;
                float4 itv = *(const float4*)row;
                float2 v0 = up2(acc[i][0]);
                float2 v1 = up2(acc[i][1]);
                float hh[4] = { v0.x + bhv[0], v0.y + bhv[1],
                                v1.x + bhv[2], v1.y + bhv[3] };
                float f[4] = { itv.x, itv.y, itv.z, itv.w };
#pragma unroll
                for (int j = 0; j < 4; j++) {
                    float a = reluN(f[j] + hh[j]);
                    f[j] = reluN(a + hh[j]);
                }
                *(float4*)row = make_float4(f[0], f[1], f[2], f[3]);
            }
        }
        if (b < Bn - 1) gbar((unsigned)(b + 1) * NCTA);
    }
}

// ============================================================================
// final_kernel: out[b,p,c] = (bf[p]+sum_k h[c,k]*Wf[p,k] >= 0) ? 1 : 0 (v1)
// ============================================================================
__global__ void __launch_bounds__(192) final_kernel(
    const float* __restrict__ Wf, const float* __restrict__ bf,
    float* __restrict__ out)
{
    __shared__ __align__(16) float As[16][36];
    __shared__ __align__(16) float Bs[16][100];
    const int b  = blockIdx.y;
    const int m0 = blockIdx.x * 32;
    const int t  = threadIdx.x;
    const int tm = t & 7, tn = t >> 3;

    ull acc[4][2];
#pragma unroll
    for (int i = 0; i < 4; i++) { acc[i][0] = 0ull; acc[i][1] = 0ull; }

    const float* hb = g_scr + (size_t)b * Cn * Hn;
    const int la_c = t >> 2, la_k = (t & 3) * 4;
    const int lb_p = t % 96, lb_k = (t / 96) * 8;

    for (int k0 = 0; k0 < Hn; k0 += 16) {
        if (t < 128) {
            int c = m0 + la_c;
            if (c < Cn) {
                float4 v = *(const float4*)(hb + (size_t)c * Hn + k0 + la_k);
                As[la_k + 0][la_c] = v.x; As[la_k + 1][la_c] = v.y;
                As[la_k + 2][la_c] = v.z; As[la_k + 3][la_c] = v.w;
            } else {
#pragma unroll
                for (int j = 0; j < 4; j++) As[la_k + j][la_c] = 0.f;
            }
        }
        {
            const float* src = Wf + (size_t)lb_p * Hn + k0 + lb_k;
            float4 v0 = *(const float4*)(src);
            float4 v1 = *(const float4*)(src + 4);
            Bs[lb_k + 0][lb_p] = v0.x; Bs[lb_k + 1][lb_p] = v0.y;
            Bs[lb_k + 2][lb_p] = v0.z; Bs[lb_k + 3][lb_p] = v0.w;
            Bs[lb_k + 4][lb_p] = v1.x; Bs[lb_k + 5][lb_p] = v1.y;
            Bs[lb_k + 6][lb_p] = v1.z; Bs[lb_k + 7][lb_p] = v1.w;
        }
        __syncthreads();
#pragma unroll
        for (int kk = 0; kk < 16; kk++) {
            float4 a = *(const float4*)&As[kk][tm * 4];
            ulonglong2 bb = *(const ulonglong2*)&Bs[kk][tn * 4];
            ull a0 = dup2(a.x), a1 = dup2(a.y), a2 = dup2(a.z), a3 = dup2(a.w);
            fma2(acc[0][0], a0, bb.x); fma2(acc[0][1], a0, bb.y);
            fma2(acc[1][0], a1, bb.x); fma2(acc[1][1], a1, bb.y);
            fma2(acc[2][0], a2, bb.x); fma2(acc[2][1], a2, bb.y);
            fma2(acc[3][0], a3, bb.x); fma2(acc[3][1], a3, bb.y);
        }
        __syncthreads();
    }
    float bfv[4];
#pragma unroll
    for (int j = 0; j < 4; j++) bfv[j] = bf[tn * 4 + j];
#pragma unroll
    for (int i = 0; i < 4; i++) {
        int c = m0 + tm * 4 + i;
        if (c < Cn) {
            float2 v0 = up2(acc[i][0]);
            float2 v1 = up2(acc[i][1]);
            float z[4] = { v0.x + bfv[0], v0.y + bfv[1],
                           v1.x + bfv[2], v1.y + bfv[3] };
            size_t base = ((size_t)b * Pn + tn * 4) * Cn + c;
#pragma unroll
            for (int j = 0; j < 4; j++)
                out[base + (size_t)j * Cn] = (z[j] >= 0.f) ? 1.f : 0.f;
        }
    }
}

// ============================================================================
extern "C" void kernel_launch(void* const* d_in, const int* in_sizes, int n_in,
                              void* d_out, int out_size) {
    const float* x  = (const float*)d_in[0];
    const float* Wi = (const float*)d_in[1];
    const float* bi = (const float*)d_in[2];
    const float* Wh = (const float*)d_in[3];
    const float* bh = (const float*)d_in[4];
    const float* Wf = (const float*)d_in[5];
    const float* bf = (const float*)d_in[6];
    float* out = (float*)d_out;

    const int smem = (512 * 64 + 2 * KT * 36) * 4;  // 149504 B
    cudaFuncSetAttribute(rnn_kernel,
                         cudaFuncAttributeMaxDynamicSharedMemorySize, smem);

    reset_bar_kernel<<<1, 1>>>();
    it_kernel<<<dim3(8, 6, Bn), 128>>>(x, Wi, bi);
    rnn_kernel<<<NCTA, 128, smem>>>(Wh, bh);
    final_kernel<<<dim3(11, Bn), 192>>>(Wf, bf, out);
}